// round 6
// baseline (speedup 1.0000x reference)
#include <cuda_runtime.h>
#include <math.h>

#define BATCH 8
#define HEADS 12
#define SEQ   512
#define DMODEL 768
#define DHEAD 64
#define SCALE 0.03608439182435161f   /* 1/sqrt(768) */

#define PROJ_ELEMS (BATCH*HEADS*SEQ*DHEAD)
#define NBLK_ATTN (16*HEADS*BATCH)
#define P_ELEMS ((size_t)BATCH*HEADS*SEQ*SEQ)
#define XN (BATCH*SEQ*DMODEL)
#define WN (DMODEL*DMODEL)

__device__ float g_ql[PROJ_ELEMS];
__device__ float g_qr[PROJ_ELEMS];
__device__ float g_q [PROJ_ELEMS];
__device__ float g_kl[PROJ_ELEMS];
__device__ float g_kr[PROJ_ELEMS];
__device__ float g_k [PROJ_ELEMS];
__device__ double g_partial[NBLK_ATTN];

// rna-tf32 pre-rounded copies of inputs/weights
__device__ float g_xq[XN];
__device__ float g_xk[XN];
__device__ float g_w6[6][WN];

struct ProjParams {
  const float* B[6];
};
struct PreSrc {
  const float* p[8];
  int len4[8];
};

__device__ __forceinline__ unsigned tf32rna(float f) {
  unsigned u;
  asm("cvt.rna.tf32.f32 %0, %1;" : "=r"(u) : "f"(f));
  return u;
}
__device__ __forceinline__ void split_tf32(float x, unsigned& hi, unsigned& lo) {
  unsigned h = tf32rna(x);
  float r = x - __uint_as_float(h);
  hi = h;
  lo = tf32rna(r);
}
__device__ __forceinline__ void mma_tf32(float* c, const unsigned* a, const unsigned* b) {
  asm volatile(
    "mma.sync.aligned.m16n8k8.row.col.f32.tf32.tf32.f32 "
    "{%0,%1,%2,%3},{%4,%5,%6,%7},{%8,%9},{%0,%1,%2,%3};"
    : "+f"(c[0]), "+f"(c[1]), "+f"(c[2]), "+f"(c[3])
    : "r"(a[0]), "r"(a[1]), "r"(a[2]), "r"(a[3]), "r"(b[0]), "r"(b[1]));
}
__device__ __forceinline__ void cpasync16(unsigned dst, const void* src) {
  asm volatile("cp.async.cg.shared.global [%0], [%1], 16;" :: "r"(dst), "l"(src));
}
__device__ __forceinline__ void cpcommit() {
  asm volatile("cp.async.commit_group;");
}

// ---------------------------------------------------------------------------
// Prepass: rna-round inputs and weights into scratch.
// ---------------------------------------------------------------------------
__global__ void prepass(PreSrc ps) {
  const int seg = blockIdx.y;
  float* dst;
  switch (seg) {
    case 0: dst = g_xq; break;
    case 1: dst = g_xk; break;
    default: dst = g_w6[seg-2]; break;
  }
  const float4* src = (const float4*)ps.p[seg];
  float4* d4 = (float4*)dst;
  const int n4 = ps.len4[seg];
  for (int i = blockIdx.x*blockDim.x + threadIdx.x; i < n4; i += gridDim.x*blockDim.x) {
    float4 v = src[i];
    v.x = __uint_as_float(tf32rna(v.x));
    v.y = __uint_as_float(tf32rna(v.y));
    v.z = __uint_as_float(tf32rna(v.z));
    v.w = __uint_as_float(tf32rna(v.w));
    d4[i] = v;
  }
}

// ---------------------------------------------------------------------------
// Projection GEMM (tf32, pre-rounded data), 2-stage cp.async pipeline.
// ---------------------------------------------------------------------------
#define PA_STRIDE 36
#define PB_STRIDE 136
#define PSTAGE_WORDS (128*PA_STRIDE + 32*PB_STRIDE)

__global__ __launch_bounds__(256)
void proj_tc(ProjParams pp) {
  extern __shared__ float psm[];
  const int widx = blockIdx.z;
  const int side = widx / 3;
  const float* __restrict__ X  = side ? g_xk : g_xq;
  const float* __restrict__ W  = g_w6[widx];
  const float* __restrict__ Bv = pp.B[widx];
  const int m0 = blockIdx.x * 128;
  const int n0 = blockIdx.y * 128;
  const float scale = (side == 0) ? SCALE : 1.0f;

  float* outp;
  switch (widx) {
    case 0: outp = g_ql; break;
    case 1: outp = g_qr; break;
    case 2: outp = g_q;  break;
    case 3: outp = g_kl; break;
    case 4: outp = g_kr; break;
    default: outp = g_k; break;
  }

  const int tid = threadIdx.x;
  const int lane = tid & 31;
  const int warp = tid >> 5;
  const int warpM = warp >> 2;
  const int warpN = warp & 3;
  const int grp = lane >> 2;
  const int tig = lane & 3;

  const unsigned smem_base = (unsigned)__cvta_generic_to_shared(psm);

  auto issue_stage = [&](int s, int kt) {
    const unsigned abase = smem_base + s*PSTAGE_WORDS*4;
    const unsigned bbase = abase + 128*PA_STRIDE*4;
    const int k0 = kt*32;
#pragma unroll
    for (int it = 0; it < 4; ++it) {
      int idx = it*256 + tid;
      int row = idx >> 3;
      int c4  = idx & 7;
      cpasync16(abase + (row*PA_STRIDE + c4*4)*4,
                X + (size_t)(m0+row)*DMODEL + k0 + c4*4);
    }
#pragma unroll
    for (int it = 0; it < 4; ++it) {
      int idx = it*256 + tid;
      int krow = idx >> 5;
      int c4   = idx & 31;
      cpasync16(bbase + (krow*PB_STRIDE + c4*4)*4,
                W + (size_t)(k0+krow)*DMODEL + n0 + c4*4);
    }
    cpcommit();
  };

  float acc[4][4][4];
#pragma unroll
  for (int i=0;i<4;i++)
#pragma unroll
    for (int j=0;j<4;j++)
#pragma unroll
      for (int r=0;r<4;r++) acc[i][j][r]=0.f;

  issue_stage(0, 0);

  const int NK = DMODEL/32;
  for (int kt = 0; kt < NK; ++kt) {
    const int cur = kt & 1;
    if (kt + 1 < NK) {
      issue_stage(cur ^ 1, kt + 1);
      asm volatile("cp.async.wait_group 1;");
    } else {
      asm volatile("cp.async.wait_group 0;");
    }
    __syncthreads();

    const unsigned* As = (const unsigned*)(psm + cur*PSTAGE_WORDS);
    const unsigned* Bs = As + 128*PA_STRIDE;

#pragma unroll
    for (int kk = 0; kk < 4; ++kk) {
      const int k8 = kk*8;
      unsigned afrag[4][4];
#pragma unroll
      for (int mi = 0; mi < 4; ++mi) {
        int r = warpM*64 + mi*16 + grp;
        afrag[mi][0] = As[r*PA_STRIDE + k8 + tig];
        afrag[mi][1] = As[(r+8)*PA_STRIDE + k8 + tig];
        afrag[mi][2] = As[r*PA_STRIDE + k8 + tig + 4];
        afrag[mi][3] = As[(r+8)*PA_STRIDE + k8 + tig + 4];
      }
      unsigned bfrag[4][2];
#pragma unroll
      for (int nj = 0; nj < 4; ++nj) {
        int c = warpN*32 + nj*8 + grp;
        bfrag[nj][0] = Bs[(k8 + tig)*PB_STRIDE + c];
        bfrag[nj][1] = Bs[(k8 + tig + 4)*PB_STRIDE + c];
      }
#pragma unroll
      for (int mi = 0; mi < 4; ++mi)
#pragma unroll
        for (int nj = 0; nj < 4; ++nj)
          mma_tf32(acc[mi][nj], afrag[mi], bfrag[nj]);
    }
    __syncthreads();
  }

#pragma unroll
  for (int mi = 0; mi < 4; ++mi) {
#pragma unroll
    for (int nj = 0; nj < 4; ++nj) {
      const int row = m0 + warpM*64 + mi*16 + grp;
      const int col = n0 + warpN*32 + nj*8 + tig*2;
      const int hh = col >> 6;
      const int dk = col & 63;
      const float2 bias = *(const float2*)(Bv + col);
      {
        const int m = row;
        const int bb = m >> 9, s = m & 511;
        float2 v;
        v.x = (acc[mi][nj][0] + bias.x) * scale;
        v.y = (acc[mi][nj][1] + bias.y) * scale;
        *(float2*)&outp[(((size_t)bb*HEADS + hh)*SEQ + s)*DHEAD + dk] = v;
      }
      {
        const int m = row + 8;
        const int bb = m >> 9, s = m & 511;
        float2 v;
        v.x = (acc[mi][nj][2] + bias.x) * scale;
        v.y = (acc[mi][nj][3] + bias.y) * scale;
        *(float2*)&outp[(((size_t)bb*HEADS + hh)*SEQ + s)*DHEAD + dk] = v;
      }
    }
  }
}

// ---------------------------------------------------------------------------
// Warp utilities
// ---------------------------------------------------------------------------
__device__ __forceinline__ float warpMax(float x) {
#pragma unroll
  for (int off=16; off>0; off>>=1) x = fmaxf(x, __shfl_xor_sync(0xffffffffu, x, off));
  return x;
}
__device__ __forceinline__ float warpSum(float x) {
#pragma unroll
  for (int off=16; off>0; off>>=1) x += __shfl_xor_sync(0xffffffffu, x, off);
  return x;
}
__device__ __forceinline__ float prefixIncl(float x, int lane) {
#pragma unroll
  for (int off=1; off<32; off<<=1) {
    float t = __shfl_up_sync(0xffffffffu, x, off);
    if (lane >= off) x += t;
  }
  return x;
}
__device__ __forceinline__ float suffixIncl(float x, int lane) {
#pragma unroll
  for (int off=1; off<32; off<<=1) {
    float t = __shfl_down_sync(0xffffffffu, x, off);
    if (lane + off < 32) x += t;
  }
  return x;
}

// ---------------------------------------------------------------------------
// Fused attention: one block per (b, h, 32-row q-tile); 512 threads (16 warps).
// Score GEMMs use 3xTF32 split MMA. ILP scans. float4 final phase.
// ---------------------------------------------------------------------------
#define QS_STRIDE 68
#define KT_STRIDE 68
#define ATHREADS 512

__global__ __launch_bounds__(ATHREADS, 1)
void attn_kernel(const float* __restrict__ mask,
                 const float* __restrict__ span,
                 float* __restrict__ out) {
  extern __shared__ float smbuf[];
  float* Qs = smbuf;                     // [3][32][68] raw fp32
  float* SL = Qs + 3*32*QS_STRIDE;       // [32][512]
  float* SR = SL + 32*SEQ;               // [32][512]
  float* KT = SR + 32*SEQ;               // [128][68] raw fp32
  float* RM = KT + 128*KT_STRIDE;        // [512]

  __shared__ float wsum[16];

  const int tid = threadIdx.x;
  const int lane = tid & 31;
  const int wid = tid >> 5;              // 0..15
  const int grp = lane >> 2;
  const int tig = lane & 3;
  const int q0 = blockIdx.x * 32;
  const int h = blockIdx.y;
  const int b = blockIdx.z;
  const int bh = (b*HEADS + h)*SEQ;

  // ---- load Q rows (3 branches) + row mask ----
#pragma unroll
  for (int it = 0; it < 3; ++it) {
    int idx = it*ATHREADS + tid;     // 1536 float4
    int br = idx >> 9;
    int rem = idx & 511;
    int q = rem >> 4;
    int dc = rem & 15;
    const float* src = (br == 0) ? g_ql : ((br == 1) ? g_qr : g_q);
    float4 v = *(const float4*)(src + (size_t)(bh + q0 + q)*DHEAD + dc*4);
    *(float4*)&Qs[(br*32 + q)*QS_STRIDE + dc*4] = v;
  }
  if (tid < SEQ) {
    float mv = mask[b*SEQ + tid];
    RM[tid] = (mv == -10000.0f) ? 1e9f : mv;
  }
  __syncthreads();

  // ---- score phase (3xTF32): each warp computes 32x8 slice per 128-key tile
  auto scorePhase = [&](const float* __restrict__ Kbuf, float* __restrict__ dest, int br) {
    for (int kt = 0; kt < 4; ++kt) {
      __syncthreads();   // KT safe to overwrite
#pragma unroll
      for (int it = 0; it < 4; ++it) {
        int idx = it*ATHREADS + tid;   // 2048 float4 = 128 rows x 16 chunks
        int kl = idx >> 4;
        int dc = idx & 15;
        float4 v = *(const float4*)(Kbuf + (size_t)(bh + kt*128 + kl)*DHEAD + dc*4);
        *(float4*)&KT[kl*KT_STRIDE + dc*4] = v;
      }
      __syncthreads();

      float acc[2][4];
#pragma unroll
      for (int i=0;i<2;i++)
#pragma unroll
        for (int r=0;r<4;r++) acc[i][r]=0.f;

#pragma unroll
      for (int kk = 0; kk < 8; ++kk) {
        const int k8 = kk*8;
        unsigned ahi[2][4], alo[2][4];
#pragma unroll
        for (int mi = 0; mi < 2; ++mi) {
          int r = br*32 + mi*16 + grp;
          split_tf32(Qs[r*QS_STRIDE + k8 + tig],       ahi[mi][0], alo[mi][0]);
          split_tf32(Qs[(r+8)*QS_STRIDE + k8 + tig],   ahi[mi][1], alo[mi][1]);
          split_tf32(Qs[r*QS_STRIDE + k8 + tig + 4],   ahi[mi][2], alo[mi][2]);
          split_tf32(Qs[(r+8)*QS_STRIDE + k8 + tig+4], ahi[mi][3], alo[mi][3]);
        }
        unsigned bhi[2], blo[2];
        {
          int n = wid*8 + grp;
          split_tf32(KT[n*KT_STRIDE + k8 + tig],     bhi[0], blo[0]);
          split_tf32(KT[n*KT_STRIDE + k8 + tig + 4], bhi[1], blo[1]);
        }
#pragma unroll
        for (int mi = 0; mi < 2; ++mi) {
          mma_tf32(acc[mi], ahi[mi], blo);
          mma_tf32(acc[mi], alo[mi], bhi);
          mma_tf32(acc[mi], ahi[mi], bhi);
        }
      }

      // write 32x8 slice
#pragma unroll
      for (int mi = 0; mi < 2; ++mi) {
        const int row = mi*16 + grp;
        const int col = kt*128 + wid*8 + tig*2;
        *(float2*)&dest[row*SEQ + col]     = make_float2(acc[mi][0], acc[mi][1]);
        *(float2*)&dest[(row+8)*SEQ + col] = make_float2(acc[mi][2], acc[mi][3]);
      }
    }
    __syncthreads();
  };

  // ================= branch L: theta_l -> inclusive prefix cumsum =========
  scorePhase(g_kl, SL, 0);
#pragma unroll
  for (int r = 0; r < 2; ++r) {
    const int q = wid*2 + r;
    const int qg = q0 + q;
    float v[16];
    float mx = -1e30f;
#pragma unroll
    for (int jj=0;jj<16;jj++) {
      int k = lane + 32*jj;
      float x = SL[q*SEQ + k];
      v[jj] = (k <= qg) ? x : -1e30f;
      mx = fmaxf(mx, v[jj]);
    }
    mx = warpMax(mx);
    float ssum = 0.f;
#pragma unroll
    for (int jj=0;jj<16;jj++) {
      int k = lane + 32*jj;
      v[jj] = (k <= qg) ? __expf(v[jj]-mx) : 0.f;
      ssum += v[jj];
    }
    ssum = warpSum(ssum);
    float inv = 1.0f/ssum;
    // ILP scan: 16 independent warp-scans, then serial register prefix of totals
    float s[16], tot[16];
#pragma unroll
    for (int jj=0;jj<16;jj++) s[jj] = prefixIncl(v[jj]*inv, lane);
#pragma unroll
    for (int jj=0;jj<16;jj++) tot[jj] = __shfl_sync(0xffffffffu, s[jj], 31);
    float off = 0.f;
#pragma unroll
    for (int jj=0;jj<16;jj++) {
      SL[q*SEQ + lane + 32*jj] = s[jj] + off;
      off += tot[jj];
    }
  }
  __syncthreads();

  // ===== branch R: theta_r -> inclusive suffix cumsum; SL *= SR ===========
  scorePhase(g_kr, SR, 1);
#pragma unroll
  for (int r = 0; r < 2; ++r) {
    const int q = wid*2 + r;
    const int qg = q0 + q;
    float v[16];
    float mx = -1e30f;
#pragma unroll
    for (int jj=0;jj<16;jj++) {
      int k = lane + 32*jj;
      float x = SR[q*SEQ + k];
      v[jj] = (k >= qg) ? x : -1e30f;
      mx = fmaxf(mx, v[jj]);
    }
    mx = warpMax(mx);
    float ssum = 0.f;
#pragma unroll
    for (int jj=0;jj<16;jj++) {
      int k = lane + 32*jj;
      v[jj] = (k >= qg) ? __expf(v[jj]-mx) : 0.f;
      ssum += v[jj];
    }
    ssum = warpSum(ssum);
    float inv = 1.0f/ssum;
    float s[16], tot[16];
#pragma unroll
    for (int jj=0;jj<16;jj++) s[jj] = suffixIncl(v[jj]*inv, lane);
#pragma unroll
    for (int jj=0;jj<16;jj++) tot[jj] = __shfl_sync(0xffffffffu, s[jj], 0);
    float off = 0.f;
#pragma unroll
    for (int jj=15;jj>=0;jj--) {
      SL[q*SEQ + lane + 32*jj] *= (s[jj] + off);
      off += tot[jj];
    }
  }
  __syncthreads();

  // ===== main branch: p = softmax((scores - rm_q - rm_k) * soft_Mask) =====
  scorePhase(g_k, SR, 2);
  float bce_acc = 0.f;
#pragma unroll
  for (int r = 0; r < 2; ++r) {
    const int q = wid*2 + r;
    const int qg = q0 + q;
    const float rmq = RM[qg];
    float4 v4[4];
    float mx = -1e30f;
#pragma unroll
    for (int jj=0;jj<4;jj++) {
      int k = lane*4 + 128*jj;
      float4 raw = *(const float4*)&SR[q*SEQ + k];
      float4 m   = *(const float4*)&SL[q*SEQ + k];
      float4 rm  = *(const float4*)&RM[k];
      float4 val;
      val.x = (raw.x - rmq - rm.x) * m.x;
      val.y = (raw.y - rmq - rm.y) * m.y;
      val.z = (raw.z - rmq - rm.z) * m.z;
      val.w = (raw.w - rmq - rm.w) * m.w;
      v4[jj] = val;
      mx = fmaxf(mx, fmaxf(fmaxf(val.x, val.y), fmaxf(val.z, val.w)));
    }
    mx = warpMax(mx);
    float ssum = 0.f;
#pragma unroll
    for (int jj=0;jj<4;jj++) {
      v4[jj].x = __expf(v4[jj].x - mx);
      v4[jj].y = __expf(v4[jj].y - mx);
      v4[jj].z = __expf(v4[jj].z - mx);
      v4[jj].w = __expf(v4[jj].w - mx);
      ssum += v4[jj].x + v4[jj].y + v4[jj].z + v4[jj].w;
    }
    ssum = warpSum(ssum);
    float inv = 1.0f/ssum;
    const size_t orow = ((size_t)(b*HEADS + h)*SEQ + qg)*SEQ;
    const size_t srow = ((size_t)(h*BATCH + b)*SEQ + qg)*SEQ;
#pragma unroll
    for (int jj=0;jj<4;jj++) {
      int k = lane*4 + 128*jj;
      float4 p;
      p.x = v4[jj].x*inv; p.y = v4[jj].y*inv;
      p.z = v4[jj].z*inv; p.w = v4[jj].w*inv;
      *(float4*)&out[orow + k] = p;
      float4 sp = *(const float4*)&span[srow + k];
      // BCE identity: log1p(exp(p)) - s*p ; p in [0,1] so 1+exp(p) in [2,3.72]
      bce_acc += __logf(1.f + __expf(p.x)) - sp.x*p.x;
      bce_acc += __logf(1.f + __expf(p.y)) - sp.y*p.y;
      bce_acc += __logf(1.f + __expf(p.z)) - sp.z*p.z;
      bce_acc += __logf(1.f + __expf(p.w)) - sp.w*p.w;
    }
  }

  // ---- block reduce BCE partial -> g_partial ----
  bce_acc = warpSum(bce_acc);
  if (lane == 0) wsum[wid] = bce_acc;
  __syncthreads();
  if (tid == 0) {
    double s = 0.0;
#pragma unroll
    for (int w=0;w<16;w++) s += (double)wsum[w];
    g_partial[(blockIdx.z*HEADS + blockIdx.y)*16 + blockIdx.x] = s;
  }
}

// ---------------------------------------------------------------------------
// Final loss reduction
// ---------------------------------------------------------------------------
__global__ void loss_reduce(float* __restrict__ out, int out_size) {
  __shared__ double red[256];
  int tid = threadIdx.x;
  double s = 0.0;
  for (int i = tid; i < NBLK_ATTN; i += 256) s += g_partial[i];
  red[tid] = s;
  __syncthreads();
  for (int off = 128; off > 0; off >>= 1) {
    if (tid < off) red[tid] += red[tid + off];
    __syncthreads();
  }
  if (tid == 0) out[out_size - 1] = (float)(red[0] / (double)P_ELEMS);
}

// ---------------------------------------------------------------------------
extern "C" void kernel_launch(void* const* d_in, const int* in_sizes, int n_in,
                              void* d_out, int out_size) {
  const float* query = (const float*)d_in[0];
  const float* key_t = (const float*)d_in[1];
  const float* mask  = (const float*)d_in[2];
  const float* span  = (const float*)d_in[3];

  PreSrc ps;
  ps.p[0] = query;                  ps.len4[0] = XN/4;
  ps.p[1] = key_t;                  ps.len4[1] = XN/4;
  ps.p[2] = (const float*)d_in[4];  ps.len4[2] = WN/4;  // Wql
  ps.p[3] = (const float*)d_in[8];  ps.len4[3] = WN/4;  // Wqr
  ps.p[4] = (const float*)d_in[12]; ps.len4[4] = WN/4;  // Wq
  ps.p[5] = (const float*)d_in[6];  ps.len4[5] = WN/4;  // Wkl
  ps.p[6] = (const float*)d_in[10]; ps.len4[6] = WN/4;  // Wkr
  ps.p[7] = (const float*)d_in[14]; ps.len4[7] = WN/4;  // Wk

  ProjParams pp;
  pp.B[0] = (const float*)d_in[5];   // bql
  pp.B[1] = (const float*)d_in[9];   // bqr
  pp.B[2] = (const float*)d_in[13];  // bq
  pp.B[3] = (const float*)d_in[7];   // bkl
  pp.B[4] = (const float*)d_in[11];  // bkr
  pp.B[5] = (const float*)d_in[15];  // bk

  float* out = (float*)d_out;

  const size_t psmem = (size_t)(2*PSTAGE_WORDS) * sizeof(float);
  const size_t asmem = (size_t)(3*32*QS_STRIDE + 32*SEQ + 32*SEQ + 128*KT_STRIDE + SEQ) * sizeof(float);
  static int attr_set = 0;
  if (!attr_set) {
    cudaFuncSetAttribute(proj_tc, cudaFuncAttributeMaxDynamicSharedMemorySize, (int)psmem);
    cudaFuncSetAttribute(attn_kernel, cudaFuncAttributeMaxDynamicSharedMemorySize, (int)asmem);
    attr_set = 1;
  }

  prepass<<<dim3(512, 8), 256>>>(ps);

  dim3 pgrid(32, 6, 6);
  proj_tc<<<pgrid, 256, psmem>>>(pp);

  dim3 agrid(SEQ/32, HEADS, BATCH);
  attn_kernel<<<agrid, ATHREADS, asmem>>>(mask, span, out);

  loss_reduce<<<1, 256>>>(out, out_size);
}